// round 17
// baseline (speedup 1.0000x reference)
#include <cuda_runtime.h>
#include <cuda_fp16.h>
#include <cstdint>
#include <cstddef>

// ---------------- problem constants ----------------
#define NSAMP   4096
#define IDIM    512
#define HDIM    128
#define LSTRIDE (HDIM + HDIM*HDIM)       // 16512 rows of W per layer
#define NLAYER  3

// ---------------- tiling ----------------
#define NB      32                        // samples per CTA (GEMM N)
#define CHUNKS  129                       // 128 weight chunks + 1 x-chunk
#define SPC     8                         // 64-k slabs per chunk (K=512) = 2 quads
#define PSEUDO  4                         // bias-fold pseudo slabs (3 live + 1 zero pad)
#define SPL     (CHUNKS*SPC + PSEUDO)     // 1036 slabs per layer (quad-aligned)
#define NSLAB   (NLAYER*SPL)              // 3108 slabs total (multiple of 4)

#define WSLAB   16384                     // [128 x 64] fp16 single image, SW128
#define ZSLAB   4096                      // [32 x 64]  fp16 single image, SW128

#define HP      132                       // hs pitch (floats)

#define OFF_W   0                         // 8 * 16384 = 131072 (8-slot ring, 2 quads)
#define OFF_Z   (8*WSLAB)                 // 8 * 4096 = 32768 (first 16KB doubles as grid)
#define OFF_H   (OFF_Z + 8*ZSLAB)
#define OFF_MB  (OFF_H + NB*HP*4)         // 2 mbarriers (8B each)
#define SMEM_ALLOC (OFF_MB + 64 + 1024)

#define THREADS 512                       // 16 warps: 4 q-blocks x 4 k-steps

#define SW128(x) ((x) ^ (((x) >> 3) & 0x70))

// ---------------- ptx helpers ----------------
__device__ __forceinline__ uint32_t smem_u32(const void* p) {
    uint32_t a;
    asm("{ .reg .u64 t; cvta.to.shared.u64 t, %1; cvt.u32.u64 %0, t; }" : "=r"(a) : "l"(p));
    return a;
}
__device__ __forceinline__ void cp16(uint32_t s, const void* g) {
    asm volatile("cp.async.cg.shared.global [%0], [%1], 16;" :: "r"(s), "l"(g));
}
#define CP_COMMIT() asm volatile("cp.async.commit_group;" ::: "memory")
#define CP_WAIT0()  asm volatile("cp.async.wait_group 0;" ::: "memory")

// Bulk async copy (single UBLKCP; completion via mbarrier complete_tx).
__device__ __forceinline__ void bulk_cp(uint32_t dst, const void* src,
                                        uint32_t bytes, uint32_t mbar) {
    asm volatile(
        "cp.async.bulk.shared::cta.global.mbarrier::complete_tx::bytes [%0], [%1], %2, [%3];"
        :: "r"(dst), "l"(src), "r"(bytes), "r"(mbar) : "memory");
}
__device__ __forceinline__ void mbar_init(uint32_t a, uint32_t cnt) {
    asm volatile("mbarrier.init.shared.b64 [%0], %1;" :: "r"(a), "r"(cnt) : "memory");
}
__device__ __forceinline__ void mbar_expect_tx(uint32_t a, uint32_t bytes) {
    asm volatile("mbarrier.arrive.expect_tx.shared.b64 _, [%0], %1;"
                 :: "r"(a), "r"(bytes) : "memory");
}
__device__ __forceinline__ void mbar_wait(uint32_t a, uint32_t parity) {
    uint32_t done;
    asm volatile(
        "{\n\t.reg .pred p;\n\t"
        "mbarrier.try_wait.parity.acquire.cta.shared::cta.b64 p, [%1], %2;\n\t"
        "selp.b32 %0, 1, 0, p;\n\t}" : "=r"(done) : "r"(a), "r"(parity) : "memory");
    if (!done) {
        asm volatile(
            "{\n\t.reg .pred P1;\n\t"
            "W_%=:\n\t"
            "mbarrier.try_wait.parity.acquire.cta.shared::cta.b64 P1, [%0], %1, 0x989680;\n\t"
            "@P1 bra.uni D_%=;\n\t"
            "bra.uni W_%=;\n\t"
            "D_%=:\n\t}" :: "r"(a), "r"(parity) : "memory");
    }
}

__device__ __forceinline__ void ldsm4(uint32_t& r0, uint32_t& r1, uint32_t& r2,
                                      uint32_t& r3, uint32_t addr) {
    asm volatile("ldmatrix.sync.aligned.m8n8.x4.shared.b16 {%0,%1,%2,%3}, [%4];"
                 : "=r"(r0), "=r"(r1), "=r"(r2), "=r"(r3) : "r"(addr));
}
__device__ __forceinline__ void mma_fp16(float* d, const uint32_t* a,
                                         uint32_t b0, uint32_t b1) {
    asm volatile(
        "mma.sync.aligned.m16n8k16.row.col.f32.f16.f16.f32 "
        "{%0,%1,%2,%3}, {%4,%5,%6,%7}, {%8,%9}, {%0,%1,%2,%3};"
        : "+f"(d[0]), "+f"(d[1]), "+f"(d[2]), "+f"(d[3])
        : "r"(a[0]), "r"(a[1]), "r"(a[2]), "r"(a[3]), "r"(b0), "r"(b1));
}
__device__ __forceinline__ unsigned packh2(float v0, float v1) {
    __half2 h = __floats2half2_rn(v0, v1);
    return *reinterpret_cast<unsigned*>(&h);
}

// W pack: per-slab 16KB single-fp16 images, pre-swizzled, in stream order.
__device__ __align__(128) unsigned char g_wpack[(size_t)NSLAB * WSLAB];

// ---------------- prep: W/b -> fp16 slab images ----------------
__global__ void prep_kernel(const float* __restrict__ W, const float* __restrict__ b) {
    const int s    = blockIdx.x;
    const int l    = s / SPL;
    const int sl   = s - l * SPL;
    const int base = l * LSTRIDE;
    unsigned char* dst = g_wpack + (size_t)s * WSLAB;

    for (int task = threadIdx.x; task < 1024; task += blockDim.x) {
        const int r = task >> 3, kb = task & 7;         // row 0..127, 8-elem k block
        float v[8];
        if (sl < CHUNKS * SPC) {
            const int c = sl >> 3, j = sl & 7;
            const int row = base + (c < HDIM ? HDIM + c * HDIM + r : r);
            const float* src = W + (size_t)row * IDIM + j * 64 + kb * 8;
            #pragma unroll
            for (int e = 0; e < 8; ++e) v[e] = src[e];
        } else {                                        // bias-fold pseudo slab (j=3: zeros)
            const int j = sl - CHUNKS * SPC;
            #pragma unroll
            for (int e = 0; e < 8; ++e) {
                const int kg = j * 64 + kb * 8 + e;
                v[e] = (kg < HDIM) ? b[base + HDIM + kg * HDIM + r]
                                   : (kg == HDIM ? b[base + r] : 0.f);
            }
        }
        const unsigned off = SW128(r * 128 + kb * 16);
        *(uint4*)(dst + off) = make_uint4(packh2(v[0], v[1]), packh2(v[2], v[3]),
                                          packh2(v[4], v[5]), packh2(v[6], v[7]));
    }
}

// Z store: 4 fp32 -> 4 fp16 (single image), swizzled, into slot slab&7.
__device__ __forceinline__ void zstore(unsigned char* sm, int slab, int zn, int zkb,
                                       float v0, float v1, float v2, float v3) {
    unsigned char* zp = sm + OFF_Z + (slab & 7) * ZSLAB;
    const unsigned zoff = SW128(zn * 128 + zkb * 8);
    *(uint2*)(zp + zoff) = make_uint2(packh2(v0, v1), packh2(v2, v3));
}

// Chunk zgen: slab (c, J); J must be a literal (xr register indexing).
#define ZGEN_CHUNK(cc, J, sslab) do { \
    const float m_ = ((cc) < HDIM) ? hs[zn*HP + (cc)] : 1.0f; \
    zstore(sm, (sslab), zn, zkb, m_*xr[J][0], m_*xr[J][1], m_*xr[J][2], m_*xr[J][3]); \
} while (0)

// Pseudo zgen: pseudo slab index J (0..3); z = h-fold columns (J=3 -> zeros).
#define ZGEN_PSEUDO(J, sslab) do { \
    float v_[4]; \
    _Pragma("unroll") \
    for (int e_ = 0; e_ < 4; ++e_) { \
        const int kgl_ = (J)*64 + zkb*4 + e_; \
        v_[e_] = (kgl_ < HDIM) ? hs[zn*HP + kgl_] : (kgl_ == HDIM ? 1.f : 0.f); \
    } \
    zstore(sm, (sslab), zn, zkb, v_[0], v_[1], v_[2], v_[3]); \
} while (0)

// ---------------- main fused kernel ----------------
__global__ void __launch_bounds__(THREADS, 1)
inet_mma_kernel(const float* __restrict__ gx_int, const float* __restrict__ gx,
                float* __restrict__ gout)
{
    extern __shared__ __align__(16) unsigned char smraw[];
    const uint32_t sb0 = smem_u32(smraw);
    const uint32_t sb  = (sb0 + 1023) & ~1023u;        // 1024-align for SW128
    unsigned char* sm  = smraw + (sb - sb0);
    float* hs = (float*)(sm + OFF_H);

    const int tid = threadIdx.x;
    const int wid = tid >> 5, lid = tid & 31;
    const int qb2 = wid >> 2;               // q-block: rows 32*qb2 .. +32
    const int kg  = wid & 3;                // this warp's k-step (16 k)
    const int n0  = blockIdx.x * NB;

    // Per-lane ldmatrix offset bases (bytes, pre-swizzle). Includes kg k-offset.
    const int g  = lid >> 3, lr = lid & 7;
    const int aoff = (32*qb2 + (g & 1)*8 + lr) * 128 + (g >> 1) * 16 + kg * 32;
    const int boff = ((g >> 1)*8 + lr) * 128 + (g & 1) * 16 + kg * 32;

    // zgen role: row zn, 4-elem k block zkb.
    const int zn = tid >> 4, zkb = tid & 15;

    // int_x held entirely in registers: xr[j][e] = x[zn, j*64 + zkb*4 + e].
    float xr[8][4];
    #pragma unroll
    for (int j = 0; j < 8; ++j) {
        const float4 t = *(const float4*)&gx_int[(size_t)(n0+zn)*IDIM + j*64 + zkb*4];
        xr[j][0] = t.x; xr[j][1] = t.y; xr[j][2] = t.z; xr[j][3] = t.w;
    }

    // 2 mbarriers (one per quad-half of the 8-slot W ring).
    if (tid == 0) { mbar_init(sb + OFF_MB, 1); mbar_init(sb + OFF_MB + 8, 1); }

    // Stage initial h = x.
    for (int i = tid; i < NB * (HDIM/4); i += THREADS) {
        int n = i >> 5, q4 = i & 31;
        cp16(sb + OFF_H + (n*HP + q4*4)*4, gx + (size_t)(n0+n)*HDIM + q4*4);
    }
    CP_COMMIT(); CP_WAIT0();
    __syncthreads();                        // hs + mbar_init visible

    // Prologue: W quads 0 (slabs 0-3) and 1 (slabs 4-7), one 64KB bulk each.
    if (tid == 0) {
        mbar_expect_tx(sb + OFF_MB, 4*WSLAB);
        bulk_cp(sb + OFF_W, g_wpack, 4*WSLAB, sb + OFF_MB);
        mbar_expect_tx(sb + OFF_MB + 8, 4*WSLAB);
        bulk_cp(sb + OFF_W + 4*WSLAB, g_wpack + (size_t)4*WSLAB, 4*WSLAB,
                sb + OFF_MB + 8);
    }

    // Quad begin (s = first slab of quad, multiple of 4): wait this quad's W,
    // CTA barrier, prefetch quad u+1 into quad u-1's (now provably free) slots.
    auto quad_begin = [&](int s) {
        mbar_wait(sb + OFF_MB + ((s >> 2) & 1) * 8, (s >> 3) & 1);
        __syncthreads();
        if (tid == 0 && s >= 4 && s + 4 < NSLAB) {
            const uint32_t mb = sb + OFF_MB + (((s + 4) >> 2) & 1) * 8;
            mbar_expect_tx(mb, 4*WSLAB);
            bulk_cp(sb + OFF_W + ((s + 4) & 7) * WSLAB,
                    g_wpack + (size_t)(s + 4) * WSLAB, 4*WSLAB, mb);
        }
    };

    int s = 0;
    for (int layer = 0; layer < NLAYER; ++layer) {
        float acc[2][4][4];                 // [q-subtile][n-tile][frag]
        #pragma unroll
        for (int st = 0; st < 2; ++st)
            #pragma unroll
            for (int t = 0; t < 4; ++t)
                #pragma unroll
                for (int i = 0; i < 4; ++i) acc[st][t][i] = 0.f;

        auto mma_slab = [&](int slab) {
            const uint32_t wb = sb + OFF_W + (slab & 7) * WSLAB;
            const uint32_t zb = sb + OFF_Z + (slab & 7) * ZSLAB;
            uint32_t ah[2][4], bh[8];
            #pragma unroll
            for (int st = 0; st < 2; ++st)
                ldsm4(ah[st][0], ah[st][1], ah[st][2], ah[st][3],
                      wb + SW128(aoff + st*2048));
            ldsm4(bh[0], bh[1], bh[2], bh[3], zb + SW128(boff));
            ldsm4(bh[4], bh[5], bh[6], bh[7], zb + SW128(boff + 2048));
            #pragma unroll
            for (int st = 0; st < 2; ++st)
                #pragma unroll
                for (int t = 0; t < 4; ++t)
                    mma_fp16(acc[st][t], ah[st], bh[2*t], bh[2*t+1]);   // w * z
        };
        auto mma_quad = [&](int s) {
            mma_slab(s); mma_slab(s+1); mma_slab(s+2); mma_slab(s+3);
        };

        if (layer == 0) {                   // Z for quad 0 (slabs 0-3)
            ZGEN_CHUNK(0, 0, 0); ZGEN_CHUNK(0, 1, 1);
            ZGEN_CHUNK(0, 2, 2); ZGEN_CHUNK(0, 3, 3);
        }

        for (int c = 0; c < CHUNKS; ++c) {
            // quad A: slabs (c, J=0..3); zgen quad B (J=4..7)
            quad_begin(s);
            ZGEN_CHUNK(c, 4, s+4); ZGEN_CHUNK(c, 5, s+5);
            ZGEN_CHUNK(c, 6, s+6); ZGEN_CHUNK(c, 7, s+7);
            mma_quad(s); s += 4;
            // quad B: slabs (c, J=4..7); zgen next chunk's quad A (or pseudo)
            quad_begin(s);
            if (c < CHUNKS - 1) {
                ZGEN_CHUNK(c+1, 0, s+4); ZGEN_CHUNK(c+1, 1, s+5);
                ZGEN_CHUNK(c+1, 2, s+6); ZGEN_CHUNK(c+1, 3, s+7);
            } else {
                ZGEN_PSEUDO(0, s+4); ZGEN_PSEUDO(1, s+5);
                ZGEN_PSEUDO(2, s+6); ZGEN_PSEUDO(3, s+7);
            }
            mma_quad(s); s += 4;
        }
        // pseudo quad: no zgen (epilogue next)
        quad_begin(s);
        mma_quad(s); s += 4;

        // ---- layer epilogue: 4-way k-group reduction via 16KB smem grid ----
        __syncthreads();                        // all MMAs done; Z area reusable
        float* grid = (float*)(sm + OFF_Z);     // [128][32]
        const int qrow = lid >> 2;
        const int nb   = 2 * (lid & 3);
        if (kg == 0) {
            #pragma unroll
            for (int st = 0; st < 2; ++st)
                #pragma unroll
                for (int t = 0; t < 4; ++t) {
                    const int q = 32*qb2 + 16*st + qrow, n = 8*t + nb;
                    *(float2*)&grid[(q    )*32 + n] = make_float2(acc[st][t][0], acc[st][t][1]);
                    *(float2*)&grid[(q + 8)*32 + n] = make_float2(acc[st][t][2], acc[st][t][3]);
                }
        }
        __syncthreads();
        #pragma unroll
        for (int p = 1; p < 4; ++p) {
            if (kg == p) {
                #pragma unroll
                for (int st = 0; st < 2; ++st)
                    #pragma unroll
                    for (int t = 0; t < 4; ++t) {
                        const int q = 32*qb2 + 16*st + qrow, n = 8*t + nb;
                        float2 v0 = *(float2*)&grid[(q    )*32 + n];
                        float2 v1 = *(float2*)&grid[(q + 8)*32 + n];
                        v0.x += acc[st][t][0]; v0.y += acc[st][t][1];
                        v1.x += acc[st][t][2]; v1.y += acc[st][t][3];
                        *(float2*)&grid[(q    )*32 + n] = v0;
                        *(float2*)&grid[(q + 8)*32 + n] = v1;
                    }
            }
            __syncthreads();
        }
        // read back: 8 cells per thread, relu -> hs or write gout
        {
            const int base = tid * 8;
            if (layer < NLAYER - 1) {
                #pragma unroll
                for (int e = 0; e < 8; ++e) {
                    const int q = (base + e) >> 5, n = (base + e) & 31;
                    hs[n*HP + q] = fmaxf(grid[base + e], 0.f);
                }
            } else {
                #pragma unroll
                for (int e = 0; e < 8; ++e) {
                    const int q = (base + e) >> 5, n = (base + e) & 31;
                    gout[(size_t)(n0 + n)*HDIM + q] = grid[base + e];
                }
            }
        }
        __syncthreads();                        // hs/grid settled

        // Z for the first quad of the NEXT layer (new hs).
        if (layer < NLAYER - 1) {
            ZGEN_CHUNK(0, 0, s);   ZGEN_CHUNK(0, 1, s+1);
            ZGEN_CHUNK(0, 2, s+2); ZGEN_CHUNK(0, 3, s+3);
        }
    }
}

extern "C" void kernel_launch(void* const* d_in, const int* in_sizes, int n_in,
                              void* d_out, int out_size)
{
    const float *int_x = nullptr, *x = nullptr, *W = nullptr, *b = nullptr;
    for (int i = 0; i < n_in; ++i) {
        const int sz = in_sizes[i];
        if      (sz == NSAMP*IDIM)          int_x = (const float*)d_in[i];
        else if (sz == NSAMP*HDIM)          x     = (const float*)d_in[i];
        else if (sz == NLAYER*LSTRIDE*IDIM) W     = (const float*)d_in[i];
        else if (sz == NLAYER*LSTRIDE)      b     = (const float*)d_in[i];
    }

    prep_kernel<<<NSLAB, 256>>>(W, b);

    cudaFuncSetAttribute(inet_mma_kernel, cudaFuncAttributeMaxDynamicSharedMemorySize,
                         SMEM_ALLOC);
    inet_mma_kernel<<<NSAMP/NB, THREADS, SMEM_ALLOC>>>(int_x, x, (float*)d_out);
}